// round 1
// baseline (speedup 1.0000x reference)
#include <cuda_runtime.h>
#include <cuda_bf16.h>
#include <cstdint>

// Problem constants
#define BATCH 32
#define C     512      // input channels (both inputs)
#define P     196      // 14*14 pixels
#define D     8192     // sketch output dim (power of two)
#define DMASK (D - 1)

// Tiling
#define C1B   128      // c1 rows per CTA
#define C2B   64       // c2 chunk per inner iteration
#define STRIDE 197     // smem row stride (odd -> conflict-free strided reads)
#define NTHREADS 256

// Sketch hash/sign tables extracted from the dense S matrices each launch.
__device__ int   g_h1[C];
__device__ int   g_h2[C];
__device__ float g_s1[C];
__device__ float g_s2[C];

// ---------------------------------------------------------------------------
// Kernel 1: extract (h, s) from dense sketch matrices S[512, 8192]
// Each row has exactly one nonzero (+-1).
// grid: (512, 2)  block: 256
// ---------------------------------------------------------------------------
__global__ void cbp_prep(const float* __restrict__ S1, const float* __restrict__ S2) {
    int row = blockIdx.x;
    const float* S = (blockIdx.y == 0) ? S1 : S2;
    const float* r = S + (size_t)row * D;
    for (int j = threadIdx.x; j < D; j += blockDim.x) {
        float v = r[j];
        if (v != 0.0f) {
            if (blockIdx.y == 0) { g_h1[row] = j; g_s1[row] = v; }
            else                 { g_h2[row] = j; g_s2[row] = v; }
        }
    }
}

// ---------------------------------------------------------------------------
// Kernel 2: zero the output (d_out is poisoned; graph replays re-run this)
// ---------------------------------------------------------------------------
__global__ void cbp_zero(float* __restrict__ out) {
    int i = blockIdx.x * blockDim.x + threadIdx.x;
    if (i < BATCH * D) out[i] = 0.0f;
}

// ---------------------------------------------------------------------------
// Kernel 3: fused Gram GEMM + count-sketch circular-conv scatter.
// grid: (4, 32)  -> blockIdx.x = c1 block (128 rows), blockIdx.y = batch
// block: 256 threads, 16x16 logical layout.
// Ownership (strided to keep scalar LDS conflict-free with odd stride):
//   c1 = ty + ii*16   (ii in 0..7)
//   c2 = tx + jj*16   (jj in 0..3)
// Dynamic smem: As[128*197] + Bs[64*197] + acc[8192]  = 184064 bytes
// ---------------------------------------------------------------------------
#define SMEM_FLOATS (C1B * STRIDE + C2B * STRIDE + D)
#define SMEM_BYTES  (SMEM_FLOATS * 4)

__global__ void __launch_bounds__(NTHREADS, 1)
cbp_main(const float* __restrict__ B1g, const float* __restrict__ B2g,
         float* __restrict__ out) {
    extern __shared__ float sm[];
    float* As  = sm;                       // [C1B][STRIDE]
    float* Bs  = sm + C1B * STRIDE;        // [C2B][STRIDE]
    float* acc = Bs + C2B * STRIDE;        // [D]

    const int b      = blockIdx.y;
    const int c1blk  = blockIdx.x * C1B;
    const int tid    = threadIdx.x;
    const int tx     = tid & 15;
    const int ty     = tid >> 4;

    // Zero the shared accumulator
    for (int i = tid; i < D; i += NTHREADS) acc[i] = 0.0f;

    // Load A tile (128 x 196), sign-folded, float4 gmem reads (196 % 4 == 0)
    {
        const float* Ag = B1g + ((size_t)b * C + c1blk) * P;
        for (int i = tid; i < C1B * (P / 4); i += NTHREADS) {
            int c  = i / (P / 4);
            int p4 = i % (P / 4);
            float4 v = ((const float4*)(Ag + (size_t)c * P))[p4];
            float  s = g_s1[c1blk + c];
            float* dst = As + c * STRIDE + p4 * 4;
            dst[0] = v.x * s; dst[1] = v.y * s; dst[2] = v.z * s; dst[3] = v.w * s;
        }
    }

    for (int cc = 0; cc < C / C2B; cc++) {
        __syncthreads();  // previous iteration's compute done reading Bs
        // Load B chunk (64 x 196), sign-folded
        {
            const float* Bg = B2g + ((size_t)b * C + cc * C2B) * P;
            for (int i = tid; i < C2B * (P / 4); i += NTHREADS) {
                int c  = i / (P / 4);
                int p4 = i % (P / 4);
                float4 v = ((const float4*)(Bg + (size_t)c * P))[p4];
                float  s = g_s2[cc * C2B + c];
                float* dst = Bs + c * STRIDE + p4 * 4;
                dst[0] = v.x * s; dst[1] = v.y * s; dst[2] = v.z * s; dst[3] = v.w * s;
            }
        }
        __syncthreads();  // tiles ready (also covers A load + acc zero on cc==0)

        // ---- 128x64 Gram tile: 8x4 per-thread microtile, packed f32x2 FMA ----
        unsigned long long accp[8][2];
        #pragma unroll
        for (int ii = 0; ii < 8; ii++) {
            accp[ii][0] = 0ull; accp[ii][1] = 0ull;
        }

        const float* ap0 = As + ty * STRIDE;   // + ii*16*STRIDE + k
        const float* bp0 = Bs + tx * STRIDE;   // + jj*16*STRIDE + k

        #pragma unroll 4
        for (int k = 0; k < P; k++) {
            float bv0 = bp0[0 * 16 * STRIDE + k];
            float bv1 = bp0[1 * 16 * STRIDE + k];
            float bv2 = bp0[2 * 16 * STRIDE + k];
            float bv3 = bp0[3 * 16 * STRIDE + k];
            unsigned long long bq0, bq1;
            asm("mov.b64 %0, {%1,%2};" : "=l"(bq0)
                : "r"(__float_as_uint(bv0)), "r"(__float_as_uint(bv1)));
            asm("mov.b64 %0, {%1,%2};" : "=l"(bq1)
                : "r"(__float_as_uint(bv2)), "r"(__float_as_uint(bv3)));
            #pragma unroll
            for (int ii = 0; ii < 8; ii++) {
                float av = ap0[ii * 16 * STRIDE + k];
                unsigned long long aq;
                asm("mov.b64 %0, {%1,%1};" : "=l"(aq) : "r"(__float_as_uint(av)));
                asm("fma.rn.f32x2 %0, %1, %2, %0;" : "+l"(accp[ii][0]) : "l"(aq), "l"(bq0));
                asm("fma.rn.f32x2 %0, %1, %2, %0;" : "+l"(accp[ii][1]) : "l"(aq), "l"(bq1));
            }
        }

        // ---- Scatter tile into shared 8192-bin accumulator ----
        int h2v[4];
        #pragma unroll
        for (int jj = 0; jj < 4; jj++) h2v[jj] = g_h2[cc * C2B + tx + jj * 16];

        #pragma unroll
        for (int ii = 0; ii < 8; ii++) {
            int h1v = g_h1[c1blk + ty + ii * 16];
            #pragma unroll
            for (int jp = 0; jp < 2; jp++) {
                unsigned int lo_u, hi_u;
                asm("mov.b64 {%0,%1}, %2;" : "=r"(lo_u), "=r"(hi_u) : "l"(accp[ii][jp]));
                atomicAdd(acc + ((h1v + h2v[jp * 2 + 0]) & DMASK), __uint_as_float(lo_u));
                atomicAdd(acc + ((h1v + h2v[jp * 2 + 1]) & DMASK), __uint_as_float(hi_u));
            }
        }
    }

    __syncthreads();
    // Merge into global output (4 CTAs per batch -> global atomics)
    float* outb = out + (size_t)b * D;
    for (int i = tid; i < D; i += NTHREADS) atomicAdd(outb + i, acc[i]);
}

// ---------------------------------------------------------------------------
// Harness entry
// Inputs (metadata order): bottom1 [32,512,14,14] f32, bottom2 [32,512,14,14] f32,
//                          S1 [512,8192] f32, S2 [512,8192] f32
// Output: [32, 8192] f32
// ---------------------------------------------------------------------------
extern "C" void kernel_launch(void* const* d_in, const int* in_sizes, int n_in,
                              void* d_out, int out_size) {
    const float* b1 = (const float*)d_in[0];
    const float* b2 = (const float*)d_in[1];
    const float* S1 = (const float*)d_in[2];
    const float* S2 = (const float*)d_in[3];
    float* out = (float*)d_out;

    cudaFuncSetAttribute(cbp_main, cudaFuncAttributeMaxDynamicSharedMemorySize,
                         SMEM_BYTES);

    cbp_prep<<<dim3(C, 2), 256>>>(S1, S2);
    cbp_zero<<<(BATCH * D + 255) / 256, 256>>>(out);
    cbp_main<<<dim3(C / C1B, BATCH), NTHREADS, SMEM_BYTES>>>(b1, b2, out);
}

// round 2
// speedup vs baseline: 1.2512x; 1.2512x over previous
#include <cuda_runtime.h>
#include <cuda_bf16.h>
#include <cstdint>

typedef unsigned long long u64;

// Problem constants
#define BATCH 32
#define C     512      // input channels (both inputs)
#define P     196      // 14*14 pixels
#define D     8192     // sketch output dim (power of two)
#define DMASK (D - 1)

// Tiling
#define C1B   128      // c1 rows per CTA
#define C2B   64       // c2 chunk per inner iteration
#define STRIDE 198     // smem row stride (even -> 8B-aligned rows; 6*tx mod 32 conflict-free)
#define NTHREADS 256

// Sketch hash/sign tables extracted from the dense S matrices each launch.
__device__ int   g_h1[C];
__device__ int   g_h2[C];
__device__ float g_s1[C];
__device__ float g_s2[C];

// ---------------------------------------------------------------------------
// Kernel 1: extract (h, s) from dense sketch matrices S[512, 8192] (one +-1
// nonzero per row), AND zero the output buffer (folded in to save a launch).
// grid: (512, 2)  block: 256
// ---------------------------------------------------------------------------
__global__ void cbp_prep(const float* __restrict__ S1, const float* __restrict__ S2,
                         float* __restrict__ out) {
    const int row = blockIdx.x;
    const float4* r = (const float4*)(((blockIdx.y == 0) ? S1 : S2) + (size_t)row * D);
    for (int j4 = threadIdx.x; j4 < D / 4; j4 += blockDim.x) {
        float4 v = r[j4];
        float nz = 0.0f; int off = 0;
        if (v.x != 0.0f) { nz = v.x; off = 0; }
        if (v.y != 0.0f) { nz = v.y; off = 1; }
        if (v.z != 0.0f) { nz = v.z; off = 2; }
        if (v.w != 0.0f) { nz = v.w; off = 3; }
        if (nz != 0.0f) {
            int j = j4 * 4 + off;
            if (blockIdx.y == 0) { g_h1[row] = j; g_s1[row] = nz; }
            else                 { g_h2[row] = j; g_s2[row] = nz; }
        }
    }
    // Zero out[32*8192]: 1024 blocks x 256 floats
    int base = (blockIdx.y * gridDim.x + blockIdx.x) * 256;
    out[base + threadIdx.x] = 0.0f;
}

// ---------------------------------------------------------------------------
// Kernel 2: fused Gram GEMM + count-sketch circular-conv scatter.
// grid: (4, 32)  block: 256 (16x16 logical).
//   c1 = ty + ii*16  (ii 0..7),  c2 = tx + jj*16 (jj 0..3)
// Inner loop: k in steps of 2; LDS.64 loads give (x[k], x[k+1]) pre-packed for
// fma.rn.f32x2; each u64 accumulator holds (even-k partial, odd-k partial) for
// one (ii,jj); lo+hi at the end is the exact Gram entry.
// Dynamic smem: As[128*198] + Bs[64*198] + acc[8192] floats = 184832 bytes
// ---------------------------------------------------------------------------
#define SMEM_FLOATS (C1B * STRIDE + C2B * STRIDE + D)
#define SMEM_BYTES  (SMEM_FLOATS * 4)

__global__ void __launch_bounds__(NTHREADS, 1)
cbp_main(const float* __restrict__ B1g, const float* __restrict__ B2g,
         float* __restrict__ out) {
    extern __shared__ float sm[];
    float* As  = sm;                       // [C1B][STRIDE]
    float* Bs  = sm + C1B * STRIDE;        // [C2B][STRIDE]
    float* acc = Bs + C2B * STRIDE;        // [D]

    const int b      = blockIdx.y;
    const int c1blk  = blockIdx.x * C1B;
    const int tid    = threadIdx.x;
    const int tx     = tid & 15;
    const int ty     = tid >> 4;

    // Zero the shared accumulator
    for (int i = tid; i < D; i += NTHREADS) acc[i] = 0.0f;

    // Load A tile (128 x 196), sign-folded, float4 gmem reads
    {
        const float* Ag = B1g + ((size_t)b * C + c1blk) * P;
        for (int i = tid; i < C1B * (P / 4); i += NTHREADS) {
            int c  = i / (P / 4);
            int p4 = i % (P / 4);
            float4 v = ((const float4*)(Ag + (size_t)c * P))[p4];
            float  s = g_s1[c1blk + c];
            float* dst = As + c * STRIDE + p4 * 4;
            dst[0] = v.x * s; dst[1] = v.y * s; dst[2] = v.z * s; dst[3] = v.w * s;
        }
    }

    const float* aRow = As + ty * STRIDE;
    const float* bRow = Bs + tx * STRIDE;

    for (int cc = 0; cc < C / C2B; cc++) {
        __syncthreads();  // previous iteration's compute done reading Bs
        // Load B chunk (64 x 196), sign-folded
        {
            const float* Bg = B2g + ((size_t)b * C + cc * C2B) * P;
            for (int i = tid; i < C2B * (P / 4); i += NTHREADS) {
                int c  = i / (P / 4);
                int p4 = i % (P / 4);
                float4 v = ((const float4*)(Bg + (size_t)c * P))[p4];
                float  s = g_s2[cc * C2B + c];
                float* dst = Bs + c * STRIDE + p4 * 4;
                dst[0] = v.x * s; dst[1] = v.y * s; dst[2] = v.z * s; dst[3] = v.w * s;
            }
        }
        __syncthreads();  // tiles ready (also covers A load + acc zero on cc==0)

        // ---- 128x64 Gram tile: 8x4 microtile, packed (even-k, odd-k) FMAs ----
        u64 accp[8][4];
        #pragma unroll
        for (int ii = 0; ii < 8; ii++)
            #pragma unroll
            for (int jj = 0; jj < 4; jj++) accp[ii][jj] = 0ull;

        #pragma unroll 2
        for (int k = 0; k < P; k += 2) {
            u64 bq[4], aq[8];
            #pragma unroll
            for (int jj = 0; jj < 4; jj++)
                bq[jj] = *(const u64*)(bRow + jj * 16 * STRIDE + k);
            #pragma unroll
            for (int ii = 0; ii < 8; ii++)
                aq[ii] = *(const u64*)(aRow + ii * 16 * STRIDE + k);
            #pragma unroll
            for (int ii = 0; ii < 8; ii++)
                #pragma unroll
                for (int jj = 0; jj < 4; jj++)
                    asm("fma.rn.f32x2 %0, %1, %2, %0;"
                        : "+l"(accp[ii][jj]) : "l"(aq[ii]), "l"(bq[jj]));
        }

        // ---- Scatter tile into shared 8192-bin accumulator ----
        int h2v[4];
        #pragma unroll
        for (int jj = 0; jj < 4; jj++) h2v[jj] = g_h2[cc * C2B + tx + jj * 16];

        #pragma unroll
        for (int ii = 0; ii < 8; ii++) {
            int h1v = g_h1[c1blk + ty + ii * 16];
            #pragma unroll
            for (int jj = 0; jj < 4; jj++) {
                unsigned int lo_u, hi_u;
                asm("mov.b64 {%0,%1}, %2;" : "=r"(lo_u), "=r"(hi_u) : "l"(accp[ii][jj]));
                float v = __uint_as_float(lo_u) + __uint_as_float(hi_u);
                atomicAdd(acc + ((h1v + h2v[jj]) & DMASK), v);
            }
        }
    }

    __syncthreads();
    // Merge into global output (4 CTAs per batch -> global atomics)
    float* outb = out + (size_t)b * D;
    for (int i = tid; i < D; i += NTHREADS) atomicAdd(outb + i, acc[i]);
}

// ---------------------------------------------------------------------------
// Harness entry
// Inputs (metadata order): bottom1 [32,512,14,14] f32, bottom2 [32,512,14,14] f32,
//                          S1 [512,8192] f32, S2 [512,8192] f32
// Output: [32, 8192] f32
// ---------------------------------------------------------------------------
extern "C" void kernel_launch(void* const* d_in, const int* in_sizes, int n_in,
                              void* d_out, int out_size) {
    const float* b1 = (const float*)d_in[0];
    const float* b2 = (const float*)d_in[1];
    const float* S1 = (const float*)d_in[2];
    const float* S2 = (const float*)d_in[3];
    float* out = (float*)d_out;

    cudaFuncSetAttribute(cbp_main, cudaFuncAttributeMaxDynamicSharedMemorySize,
                         SMEM_BYTES);

    cbp_prep<<<dim3(C, 2), 256>>>(S1, S2, out);
    cbp_main<<<dim3(C / C1B, BATCH), NTHREADS, SMEM_BYTES>>>(b1, b2, out);
}